// round 5
// baseline (speedup 1.0000x reference)
#include <cuda_runtime.h>

#define N_ROWS 65536
#define DIM    256
#define KCODES 1024

#define BM 128   // rows per block
#define BK 128   // codes per k-chunk
#define BD 32    // depth chunk

typedef unsigned long long ull;

// Scratch (no allocations allowed in kernel_launch)
__device__ float g_esq[KCODES];
__device__ float g_S[N_ROWS];
__device__ int   g_idx[N_ROWS];
__device__ float g_partials[2048];

// ---------------------------------------------------------------------------
// Kernel 0: e_sq[k] = ||codebook[k]||^2   (warp per code, order-insensitive)
// ---------------------------------------------------------------------------
__global__ void esq_kernel(const float* __restrict__ cb) {
    int warp = (blockIdx.x * blockDim.x + threadIdx.x) >> 5;
    int lane = threadIdx.x & 31;
    if (warp >= KCODES) return;
    const float4* row = (const float4*)(cb + warp * DIM);
    float s = 0.f;
    #pragma unroll
    for (int i = lane; i < DIM / 4; i += 32) {
        float4 v = row[i];
        s += v.x * v.x + v.y * v.y + v.z * v.z + v.w * v.w;
    }
    #pragma unroll
    for (int off = 16; off; off >>= 1) s += __shfl_xor_sync(0xffffffff, s, off);
    if (lane == 0) g_esq[warp] = s;
}

// ---------------------------------------------------------------------------
// Kernel 0b: S[n] = ||z[n]||^2, bit-exact IC=4 order (validated in R3),
// lane-parallel: the 16 independent fma chains map to 16 lanes (coalesced).
//   a[j] = chain_i fma(p[16i+j]);  u[l]=((a_l+a_{l+4})+a_{l+8})+a_{l+12};
//   S = (u0+u1)+(u2+u3)
// ---------------------------------------------------------------------------
__global__ void s_kernel(const float* __restrict__ z) {
    int warp = (blockIdx.x * blockDim.x + threadIdx.x) >> 5;
    int lane = threadIdx.x & 31;
    int j    = lane & 15;
    long row = (long)warp * 2 + (lane >> 4);
    const float* p = z + row * DIM;
    float a = 0.f;
    #pragma unroll
    for (int i = 0; i < 16; i++) {
        float v = p[i * 16 + j];
        a = __fmaf_rn(v, v, a);
    }
    unsigned m = 0xffffffffu;
    float t1 = __shfl_down_sync(m, a, 4, 16);
    float t2 = __shfl_down_sync(m, a, 8, 16);
    float t3 = __shfl_down_sync(m, a, 12, 16);
    float u  = __fadd_rn(__fadd_rn(__fadd_rn(a, t1), t2), t3);   // lanes j<4 valid
    float u1 = __shfl_down_sync(m, u, 1, 16);
    float u2 = __shfl_down_sync(m, u, 2, 16);
    float u3 = __shfl_down_sync(m, u, 3, 16);
    if (j == 0) g_S[row] = __fadd_rn(__fadd_rn(u, u1), __fadd_rn(u2, u3));
}

// ---------------------------------------------------------------------------
// Kernel 1: argmin over k of fl(fl(S - 2*cross) + e_sq), ties -> lowest index.
// cross: single sequential fp32 fma chain over d=0..255, computed with packed
// fma.rn.f32x2 (rows paired in lanes; per-lane rounding identical to FFMA).
// B tile stored duplicated in smem so no per-d lane-dup MOVs are needed.
// ---------------------------------------------------------------------------
__global__ __launch_bounds__(256, 2)
void argmin_kernel(const float* __restrict__ z, const float* __restrict__ cb) {
    __shared__ float As[BD][BM];        // 16 KB : z^T tile
    __shared__ float Bs2[BD][2 * BK];   // 32 KB : cb^T tile, each value duplicated

    const int tid = threadIdx.x;
    const int tx  = tid & 15;      // code group
    const int ty  = tid >> 4;      // row group
    const int row0 = blockIdx.x * BM;

    // rows handled: pair p, lane l -> r(p,l)
    //   p=0: ty*4+{0,1}; p=1: ty*4+{2,3}; p=2: 64+ty*4+{0,1}; p=3: 64+ty*4+{2,3}
    float Srow[4][2];
    #pragma unroll
    for (int p = 0; p < 4; p++)
        #pragma unroll
        for (int l = 0; l < 2; l++) {
            int r = ((p < 2) ? 0 : 64) + ty * 4 + (p & 1) * 2 + l;
            Srow[p][l] = g_S[row0 + r];
        }

    float minv[4][2];
    int   mini[4][2];
    #pragma unroll
    for (int p = 0; p < 4; p++)
        #pragma unroll
        for (int l = 0; l < 2; l++) { minv[p][l] = 3.4e38f; mini[p][l] = 0; }

    for (int kc = 0; kc < KCODES; kc += BK) {
        ull acc[4][8];
        #pragma unroll
        for (int p = 0; p < 4; p++)
            #pragma unroll
            for (int j = 0; j < 8; j++) acc[p][j] = 0ull;

        for (int dc = 0; dc < DIM; dc += BD) {
            __syncthreads();
            #pragma unroll
            for (int lph = 0; lph < 4; lph++) {
                int f  = tid + lph * 256;      // 0..1023
                int m  = f >> 3;
                int dq = (f & 7) << 2;
                float4 v = *(const float4*)(z  + (long)(row0 + m) * DIM + dc + dq);
                As[dq + 0][m] = v.x; As[dq + 1][m] = v.y;
                As[dq + 2][m] = v.z; As[dq + 3][m] = v.w;
                float4 w = *(const float4*)(cb + (long)(kc + m)  * DIM + dc + dq);
                Bs2[dq + 0][2 * m] = w.x; Bs2[dq + 0][2 * m + 1] = w.x;
                Bs2[dq + 1][2 * m] = w.y; Bs2[dq + 1][2 * m + 1] = w.y;
                Bs2[dq + 2][2 * m] = w.z; Bs2[dq + 2][2 * m + 1] = w.z;
                Bs2[dq + 3][2 * m] = w.w; Bs2[dq + 3][2 * m + 1] = w.w;
            }
            __syncthreads();

            #pragma unroll
            for (int d = 0; d < BD; d++) {
                ulonglong2 aL = *(const ulonglong2*)&As[d][ty * 4];        // p0,p1
                ulonglong2 aH = *(const ulonglong2*)&As[d][64 + ty * 4];   // p2,p3
                ulonglong2 b0 = *(const ulonglong2*)&Bs2[d][8 * tx];           // j0,j1
                ulonglong2 b1 = *(const ulonglong2*)&Bs2[d][8 * tx + 4];       // j2,j3
                ulonglong2 b2 = *(const ulonglong2*)&Bs2[d][128 + 8 * tx];     // j4,j5
                ulonglong2 b3 = *(const ulonglong2*)&Bs2[d][128 + 8 * tx + 4]; // j6,j7
                ull aq[4] = { aL.x, aL.y, aH.x, aH.y };
                ull bq[8] = { b0.x, b0.y, b1.x, b1.y, b2.x, b2.y, b3.x, b3.y };
                #pragma unroll
                for (int p = 0; p < 4; p++)
                    #pragma unroll
                    for (int j = 0; j < 8; j++)
                        asm("fma.rn.f32x2 %0, %1, %2, %0;"
                            : "+l"(acc[p][j]) : "l"(aq[p]), "l"(bq[j]));
            }
        }

        // epilogue: d = fl(fl(S - 2c) + e), strict < keeps lowest index
        #pragma unroll
        for (int j = 0; j < 8; j++) {
            int code = (j < 4) ? (tx * 4 + j) : (64 + tx * 4 + (j - 4));
            float e = g_esq[kc + code];
            #pragma unroll
            for (int p = 0; p < 4; p++) {
                float clo = __uint_as_float((unsigned)(acc[p][j] & 0xffffffffull));
                float chi = __uint_as_float((unsigned)(acc[p][j] >> 32));
                float d0 = __fadd_rn(__fadd_rn(Srow[p][0], __fmul_rn(-2.f, clo)), e);
                float d1 = __fadd_rn(__fadd_rn(Srow[p][1], __fmul_rn(-2.f, chi)), e);
                if (d0 < minv[p][0]) { minv[p][0] = d0; mini[p][0] = kc + code; }
                if (d1 < minv[p][1]) { minv[p][1] = d1; mini[p][1] = kc + code; }
            }
        }
    }

    // cross-tx reduction (16 threads share each row) — reuse As/Bs2 storage
    __syncthreads();
    float* Sval = &As[0][0];
    int*   Sidx = (int*)&Bs2[0][0];
    #pragma unroll
    for (int p = 0; p < 4; p++)
        #pragma unroll
        for (int l = 0; l < 2; l++) {
            int r = ((p < 2) ? 0 : 64) + ty * 4 + (p & 1) * 2 + l;
            Sval[r * 16 + tx] = minv[p][l];
            Sidx[r * 16 + tx] = mini[p][l];
        }
    __syncthreads();
    if (tid < BM) {
        float bv = Sval[tid * 16];
        int   bi = Sidx[tid * 16];
        #pragma unroll
        for (int t = 1; t < 16; t++) {
            float v  = Sval[tid * 16 + t];
            int   ix = Sidx[tid * 16 + t];
            if (v < bv || (v == bv && ix < bi)) { bv = v; bi = ix; }
        }
        g_idx[row0 + tid] = bi;
    }
}

// ---------------------------------------------------------------------------
// Kernel 2: z_q = codebook[idx], per-block partial sums of (z_q - z_e)^2
// ---------------------------------------------------------------------------
__global__ void gather_loss_kernel(const float* __restrict__ z,
                                   const float* __restrict__ cb,
                                   float* __restrict__ out) {
    const int b   = blockIdx.x;
    const int tid = threadIdx.x;
    float s = 0.f;
    #pragma unroll
    for (int l = 0; l < 8; l++) {
        int f   = tid + l * 256;
        int r   = f >> 6;
        int c   = (f & 63) << 2;
        int row = b * 32 + r;
        int code = g_idx[row];
        float4 q  = *(const float4*)(cb + (long)code * DIM + c);
        float4 ze = *(const float4*)(z  + (long)row  * DIM + c);
        *(float4*)(out + (long)row * DIM + c) = q;
        float dx = q.x - ze.x, dy = q.y - ze.y, dz = q.z - ze.z, dw = q.w - ze.w;
        s += dx * dx + dy * dy + dz * dz + dw * dw;
    }
    __shared__ float red[256];
    red[tid] = s;
    __syncthreads();
    #pragma unroll
    for (int off = 128; off; off >>= 1) {
        if (tid < off) red[tid] += red[tid + off];
        __syncthreads();
    }
    if (tid == 0) g_partials[b] = red[0];
}

// ---------------------------------------------------------------------------
// Kernel 3: final deterministic loss reduction; write scalar(s) after z_q
// ---------------------------------------------------------------------------
__global__ void finalize_kernel(float* __restrict__ out, int out_size) {
    __shared__ double red[256];
    const int tid = threadIdx.x;
    double s = 0.0;
    for (int i = tid; i < 2048; i += 256) s += (double)g_partials[i];
    red[tid] = s;
    __syncthreads();
    #pragma unroll
    for (int off = 128; off; off >>= 1) {
        if (tid < off) red[tid] += red[tid + off];
        __syncthreads();
    }
    if (tid == 0) {
        float loss = (float)(red[0] / (double)((long)N_ROWS * DIM));
        for (long i = (long)N_ROWS * DIM; i < (long)out_size; i++) out[i] = loss;
    }
}

// ---------------------------------------------------------------------------
extern "C" void kernel_launch(void* const* d_in, const int* in_sizes, int n_in,
                              void* d_out, int out_size) {
    const float* z  = (const float*)d_in[0];
    const float* cb = (const float*)d_in[1];
    if (n_in >= 2 && in_sizes[0] == KCODES * DIM && in_sizes[1] == N_ROWS * DIM) {
        const float* t = z; z = cb; cb = t;
    }
    float* out = (float*)d_out;

    esq_kernel<<<KCODES / 8, 256>>>(cb);
    s_kernel<<<(N_ROWS / 16), 256>>>(z);               // 8 warps/block, 2 rows/warp
    argmin_kernel<<<N_ROWS / BM, 256>>>(z, cb);        // 512 blocks
    gather_loss_kernel<<<N_ROWS / 32, 256>>>(z, cb, out);
    finalize_kernel<<<1, 256>>>(out, out_size);
}

// round 6
// speedup vs baseline: 2.1328x; 2.1328x over previous
#include <cuda_runtime.h>

#define N_ROWS 65536
#define DIM    256
#define KCODES 1024

#define BM 128
#define BN 128
#define BD 32
#define CAND_CAP (8 * 1024 * 1024)
#define MARGIN 2e-3f

typedef unsigned long long ull;

// Scratch (no allocations allowed in kernel_launch)
__device__ float    g_esq[KCODES];
__device__ float    g_S[N_ROWS];
__device__ float    g_maxm[N_ROWS];
__device__ ull      g_best[N_ROWS];
__device__ unsigned g_cand[CAND_CAP];
__device__ int      g_ncand;
__device__ float    g_partials[2048];

// ---------------------------------------------------------------------------
// Kernel 0: e_sq[k] = ||codebook[k]||^2 (order-insensitive; validated R3)
// ---------------------------------------------------------------------------
__global__ void esq_kernel(const float* __restrict__ cb) {
    int warp = (blockIdx.x * blockDim.x + threadIdx.x) >> 5;
    int lane = threadIdx.x & 31;
    if (warp >= KCODES) return;
    const float4* row = (const float4*)(cb + warp * DIM);
    float s = 0.f;
    #pragma unroll
    for (int i = lane; i < DIM / 4; i += 32) {
        float4 v = row[i];
        s += v.x * v.x + v.y * v.y + v.z * v.z + v.w * v.w;
    }
    #pragma unroll
    for (int off = 16; off; off >>= 1) s += __shfl_xor_sync(0xffffffff, s, off);
    if (lane == 0) g_esq[warp] = s;
}

// ---------------------------------------------------------------------------
// Kernel 0b: S[n] = ||z[n]||^2, bit-exact IC=4 order (validated R3/R4)
// ---------------------------------------------------------------------------
__global__ void s_kernel(const float* __restrict__ z) {
    int warp = (blockIdx.x * blockDim.x + threadIdx.x) >> 5;
    int lane = threadIdx.x & 31;
    int j    = lane & 15;
    long row = (long)warp * 2 + (lane >> 4);
    const float* p = z + row * DIM;
    float a = 0.f;
    #pragma unroll
    for (int i = 0; i < 16; i++) {
        float v = p[i * 16 + j];
        a = __fmaf_rn(v, v, a);
    }
    unsigned m = 0xffffffffu;
    float t1 = __shfl_down_sync(m, a, 4, 16);
    float t2 = __shfl_down_sync(m, a, 8, 16);
    float t3 = __shfl_down_sync(m, a, 12, 16);
    float u  = __fadd_rn(__fadd_rn(__fadd_rn(a, t1), t2), t3);
    float u1 = __shfl_down_sync(m, u, 1, 16);
    float u2 = __shfl_down_sync(m, u, 2, 16);
    float u3 = __shfl_down_sync(m, u, 3, 16);
    if (j == 0) g_S[row] = __fadd_rn(__fadd_rn(u, u1), __fadd_rn(u2, u3));
}

// ---------------------------------------------------------------------------
// Kernel 0c: init g_best / candidate counter
// ---------------------------------------------------------------------------
__global__ void init_kernel() {
    int i = blockIdx.x * blockDim.x + threadIdx.x;
    if (i < N_ROWS) g_best[i] = ~0ull;
    if (i == 0) g_ncand = 0;
}

// ---------------------------------------------------------------------------
// tf32 mma helper
// ---------------------------------------------------------------------------
__device__ __forceinline__ void mma_tf32(float acc[4],
                                         unsigned a0, unsigned a1, unsigned a2, unsigned a3,
                                         unsigned b0, unsigned b1) {
    asm volatile(
        "mma.sync.aligned.m16n8k8.row.col.f32.tf32.tf32.f32 "
        "{%0,%1,%2,%3}, {%4,%5,%6,%7}, {%8,%9}, {%0,%1,%2,%3};"
        : "+f"(acc[0]), "+f"(acc[1]), "+f"(acc[2]), "+f"(acc[3])
        : "r"(a0), "r"(a1), "r"(a2), "r"(a3), "r"(b0), "r"(b1));
}

__device__ __forceinline__ void push_cand(int row, int code) {
    int slot = atomicAdd(&g_ncand, 1);
    if (slot < CAND_CAP) g_cand[slot] = ((unsigned)row << 10) | (unsigned)code;
}

// ---------------------------------------------------------------------------
// Kernel 1: tf32 approx GEMM of m[n,k] = 2*z.cb - e_sq
//   mode 0: per-row max of m  -> g_maxm
//   mode 1: enqueue all (n,k) with m > g_maxm[n] - MARGIN
// Block: 256 thr (8 warps, 4x2 over 128 rows x 128 cols); kc loop over K.
// ---------------------------------------------------------------------------
__global__ __launch_bounds__(256, 2)
void approx_kernel(const float* __restrict__ z, const float* __restrict__ cb, int mode) {
    __shared__ unsigned uA[BM][36];   // z tile, tf32 bits, pad->conflict-free
    __shared__ unsigned uB[BN][36];   // cb tile

    const int tid  = threadIdx.x;
    const int lane = tid & 31;
    const int warp = tid >> 5;
    const int wr = warp >> 1, wc = warp & 1;
    const int g = lane >> 2, t = lane & 3;
    const int row0 = blockIdx.x * BM;

    // thread's 4 row slots: s -> r = wr*32 + (s>>1)*16 + (s&1)*8 + g
    float thr[4], runmax[4];
    #pragma unroll
    for (int s = 0; s < 4; s++) runmax[s] = -3.4e38f;
    if (mode == 1) {
        #pragma unroll
        for (int s = 0; s < 4; s++) {
            int r = wr * 32 + (s >> 1) * 16 + (s & 1) * 8 + g;
            thr[s] = g_maxm[row0 + r] - MARGIN;
        }
    }

    for (int kc = 0; kc < KCODES; kc += BN) {
        float acc[2][8][4];
        #pragma unroll
        for (int mf = 0; mf < 2; mf++)
            #pragma unroll
            for (int nf = 0; nf < 8; nf++)
                #pragma unroll
                for (int q = 0; q < 4; q++) acc[mf][nf][q] = 0.f;

        for (int dc = 0; dc < DIM; dc += BD) {
            __syncthreads();
            #pragma unroll
            for (int lph = 0; lph < 4; lph++) {
                int f  = tid + lph * 256;      // 0..1023
                int r  = f >> 3;
                int dq = (f & 7) << 2;
                float4 v = *(const float4*)(z + (size_t)(row0 + r) * DIM + dc + dq);
                asm("cvt.rna.tf32.f32 %0, %1;" : "=r"(uA[r][dq + 0]) : "f"(v.x));
                asm("cvt.rna.tf32.f32 %0, %1;" : "=r"(uA[r][dq + 1]) : "f"(v.y));
                asm("cvt.rna.tf32.f32 %0, %1;" : "=r"(uA[r][dq + 2]) : "f"(v.z));
                asm("cvt.rna.tf32.f32 %0, %1;" : "=r"(uA[r][dq + 3]) : "f"(v.w));
                float4 w = *(const float4*)(cb + (size_t)(kc + r) * DIM + dc + dq);
                asm("cvt.rna.tf32.f32 %0, %1;" : "=r"(uB[r][dq + 0]) : "f"(w.x));
                asm("cvt.rna.tf32.f32 %0, %1;" : "=r"(uB[r][dq + 1]) : "f"(w.y));
                asm("cvt.rna.tf32.f32 %0, %1;" : "=r"(uB[r][dq + 2]) : "f"(w.z));
                asm("cvt.rna.tf32.f32 %0, %1;" : "=r"(uB[r][dq + 3]) : "f"(w.w));
            }
            __syncthreads();

            #pragma unroll
            for (int ks = 0; ks < BD; ks += 8) {
                unsigned af[2][4];
                #pragma unroll
                for (int mf = 0; mf < 2; mf++) {
                    int ar = wr * 32 + mf * 16 + g;
                    af[mf][0] = uA[ar][ks + t];
                    af[mf][1] = uA[ar + 8][ks + t];
                    af[mf][2] = uA[ar][ks + t + 4];
                    af[mf][3] = uA[ar + 8][ks + t + 4];
                }
                #pragma unroll
                for (int nf = 0; nf < 8; nf++) {
                    int bn = wc * 64 + nf * 8 + g;
                    unsigned b0 = uB[bn][ks + t];
                    unsigned b1 = uB[bn][ks + t + 4];
                    mma_tf32(acc[0][nf], af[0][0], af[0][1], af[0][2], af[0][3], b0, b1);
                    mma_tf32(acc[1][nf], af[1][0], af[1][1], af[1][2], af[1][3], b0, b1);
                }
            }
        }

        // epilogue: m = 2*acc - e_sq   (c0: row g,col 2t; c1: +col; c2: row g+8; c3)
        #pragma unroll
        for (int mf = 0; mf < 2; mf++)
            #pragma unroll
            for (int nf = 0; nf < 8; nf++) {
                int c0 = kc + wc * 64 + nf * 8 + 2 * t;
                float e0 = __ldg(&g_esq[c0]);
                float e1 = __ldg(&g_esq[c0 + 1]);
                float m00 = __fmaf_rn(2.f, acc[mf][nf][0], -e0);
                float m01 = __fmaf_rn(2.f, acc[mf][nf][1], -e1);
                float m10 = __fmaf_rn(2.f, acc[mf][nf][2], -e0);
                float m11 = __fmaf_rn(2.f, acc[mf][nf][3], -e1);
                if (mode == 0) {
                    runmax[mf * 2]     = fmaxf(runmax[mf * 2],     fmaxf(m00, m01));
                    runmax[mf * 2 + 1] = fmaxf(runmax[mf * 2 + 1], fmaxf(m10, m11));
                } else {
                    int r0 = row0 + wr * 32 + mf * 16 + g;
                    if (m00 > thr[mf * 2])     push_cand(r0,     c0);
                    if (m01 > thr[mf * 2])     push_cand(r0,     c0 + 1);
                    if (m10 > thr[mf * 2 + 1]) push_cand(r0 + 8, c0);
                    if (m11 > thr[mf * 2 + 1]) push_cand(r0 + 8, c0 + 1);
                }
            }
    }

    if (mode == 0) {
        __syncthreads();
        float* Red = (float*)&uA[0][0];        // 128 x 8
        #pragma unroll
        for (int s = 0; s < 4; s++) {
            int r = wr * 32 + (s >> 1) * 16 + (s & 1) * 8 + g;
            Red[r * 8 + wc * 4 + t] = runmax[s];
        }
        __syncthreads();
        if (tid < BM) {
            float mx = Red[tid * 8];
            #pragma unroll
            for (int i = 1; i < 8; i++) mx = fmaxf(mx, Red[tid * 8 + i]);
            g_maxm[row0 + tid] = mx;
        }
    }
}

// ---------------------------------------------------------------------------
// Kernel 2: exact rescore of candidates — bit-identical to R3's winning math:
// sequential fp32 fma chain d=0..255, d = fl(fl(S-2c)+e); atomicMin on
// (distbits<<32 | code) => min dist, ties -> lowest code (jnp.argmin rule).
// ---------------------------------------------------------------------------
__global__ void rescore_kernel(const float* __restrict__ z, const float* __restrict__ cb) {
    int n = g_ncand;
    if (n > CAND_CAP) n = CAND_CAP;
    for (int i = blockIdx.x * blockDim.x + threadIdx.x; i < n; i += gridDim.x * blockDim.x) {
        unsigned pc = g_cand[i];
        int row  = pc >> 10;
        int code = pc & 1023;
        const float* zp = z  + (size_t)row  * DIM;
        const float* cp = cb + (size_t)code * DIM;
        float c = 0.f;
        #pragma unroll 8
        for (int d = 0; d < DIM; d++) c = __fmaf_rn(__ldg(zp + d), __ldg(cp + d), c);
        float dex = __fadd_rn(__fadd_rn(g_S[row], __fmul_rn(-2.f, c)), g_esq[code]);
        ull key = ((ull)__float_as_uint(dex) << 32) | (unsigned)code;
        atomicMin(&g_best[row], key);
    }
}

// ---------------------------------------------------------------------------
// Kernel 3: z_q = codebook[idx], per-block partial sums of (z_q - z_e)^2
// ---------------------------------------------------------------------------
__global__ void gather_loss_kernel(const float* __restrict__ z,
                                   const float* __restrict__ cb,
                                   float* __restrict__ out) {
    const int b   = blockIdx.x;
    const int tid = threadIdx.x;
    float s = 0.f;
    #pragma unroll
    for (int l = 0; l < 8; l++) {
        int f   = tid + l * 256;
        int r   = f >> 6;
        int c   = (f & 63) << 2;
        int row = b * 32 + r;
        int code = (int)(unsigned)(g_best[row] & 1023ull);
        float4 q  = *(const float4*)(cb + (size_t)code * DIM + c);
        float4 ze = *(const float4*)(z  + (size_t)row  * DIM + c);
        *(float4*)(out + (size_t)row * DIM + c) = q;
        float dx = q.x - ze.x, dy = q.y - ze.y, dz = q.z - ze.z, dw = q.w - ze.w;
        s += dx * dx + dy * dy + dz * dz + dw * dw;
    }
    __shared__ float red[256];
    red[tid] = s;
    __syncthreads();
    #pragma unroll
    for (int off = 128; off; off >>= 1) {
        if (tid < off) red[tid] += red[tid + off];
        __syncthreads();
    }
    if (tid == 0) g_partials[b] = red[0];
}

// ---------------------------------------------------------------------------
// Kernel 4: final deterministic loss reduction; write scalar(s) after z_q
// ---------------------------------------------------------------------------
__global__ void finalize_kernel(float* __restrict__ out, int out_size) {
    __shared__ double red[256];
    const int tid = threadIdx.x;
    double s = 0.0;
    for (int i = tid; i < 2048; i += 256) s += (double)g_partials[i];
    red[tid] = s;
    __syncthreads();
    #pragma unroll
    for (int off = 128; off; off >>= 1) {
        if (tid < off) red[tid] += red[tid + off];
        __syncthreads();
    }
    if (tid == 0) {
        float loss = (float)(red[0] / (double)((long)N_ROWS * DIM));
        for (long i = (long)N_ROWS * DIM; i < (long)out_size; i++) out[i] = loss;
    }
}

// ---------------------------------------------------------------------------
extern "C" void kernel_launch(void* const* d_in, const int* in_sizes, int n_in,
                              void* d_out, int out_size) {
    const float* z  = (const float*)d_in[0];
    const float* cb = (const float*)d_in[1];
    if (n_in >= 2 && in_sizes[0] == KCODES * DIM && in_sizes[1] == N_ROWS * DIM) {
        const float* t = z; z = cb; cb = t;
    }
    float* out = (float*)d_out;

    esq_kernel<<<KCODES / 8, 256>>>(cb);
    s_kernel<<<N_ROWS / 16, 256>>>(z);
    init_kernel<<<N_ROWS / 256, 256>>>();
    approx_kernel<<<N_ROWS / BM, 256>>>(z, cb, 0);   // pass 1: row maxima
    approx_kernel<<<N_ROWS / BM, 256>>>(z, cb, 1);   // pass 2: candidates
    rescore_kernel<<<512, 256>>>(z, cb);             // exact winners
    gather_loss_kernel<<<N_ROWS / 32, 256>>>(z, cb, out);
    finalize_kernel<<<1, 256>>>(out, out_size);
}

// round 12
// speedup vs baseline: 2.3541x; 1.1038x over previous
#include <cuda_runtime.h>

#define N_ROWS 65536
#define DIM    256
#define KCODES 1024

#define BM 128
#define BN 128
#define BD 32
#define CAND_CAP (4 * 1024 * 1024)
#define MARGIN   2e-3f

typedef unsigned long long ull;

// Scratch (no allocations allowed in kernel_launch)
__device__ float    g_esq[KCODES];
__device__ float    g_S[N_ROWS];
__device__ ull      g_best[N_ROWS];
__device__ unsigned g_cand[CAND_CAP];
__device__ int      g_ncand;
__device__ float    g_partials[2048];

// ---------------------------------------------------------------------------
// Kernel 0: e_sq[k] = ||codebook[k]||^2 (order-insensitive; validated R3)
// ---------------------------------------------------------------------------
__global__ void esq_kernel(const float* __restrict__ cb) {
    if (blockIdx.x == 0 && threadIdx.x == 0) g_ncand = 0;
    int warp = (blockIdx.x * blockDim.x + threadIdx.x) >> 5;
    int lane = threadIdx.x & 31;
    if (warp >= KCODES) return;
    const float4* row = (const float4*)(cb + warp * DIM);
    float s = 0.f;
    #pragma unroll
    for (int i = lane; i < DIM / 4; i += 32) {
        float4 v = row[i];
        s += v.x * v.x + v.y * v.y + v.z * v.z + v.w * v.w;
    }
    #pragma unroll
    for (int off = 16; off; off >>= 1) s += __shfl_xor_sync(0xffffffff, s, off);
    if (lane == 0) g_esq[warp] = s;
}

// ---------------------------------------------------------------------------
// Kernel 0b: S[n] = ||z[n]||^2, bit-exact IC=4 order (validated R3/R4).
// Also initializes g_best[row].
// ---------------------------------------------------------------------------
__global__ void s_kernel(const float* __restrict__ z) {
    int warp = (blockIdx.x * blockDim.x + threadIdx.x) >> 5;
    int lane = threadIdx.x & 31;
    int j    = lane & 15;
    long row = (long)warp * 2 + (lane >> 4);
    const float* p = z + row * DIM;
    float a = 0.f;
    #pragma unroll
    for (int i = 0; i < 16; i++) {
        float v = p[i * 16 + j];
        a = __fmaf_rn(v, v, a);
    }
    unsigned m = 0xffffffffu;
    float t1 = __shfl_down_sync(m, a, 4, 16);
    float t2 = __shfl_down_sync(m, a, 8, 16);
    float t3 = __shfl_down_sync(m, a, 12, 16);
    float u  = __fadd_rn(__fadd_rn(__fadd_rn(a, t1), t2), t3);
    float u1 = __shfl_down_sync(m, u, 1, 16);
    float u2 = __shfl_down_sync(m, u, 2, 16);
    float u3 = __shfl_down_sync(m, u, 3, 16);
    if (j == 0) {
        g_S[row]    = __fadd_rn(__fadd_rn(u, u1), __fadd_rn(u2, u3));
        g_best[row] = ~0ull;
    }
}

// ---------------------------------------------------------------------------
// tf32 mma helper
// ---------------------------------------------------------------------------
__device__ __forceinline__ void mma_tf32(float acc[4],
                                         unsigned a0, unsigned a1, unsigned a2, unsigned a3,
                                         unsigned b0, unsigned b1) {
    asm volatile(
        "mma.sync.aligned.m16n8k8.row.col.f32.tf32.tf32.f32 "
        "{%0,%1,%2,%3}, {%4,%5,%6,%7}, {%8,%9}, {%0,%1,%2,%3};"
        : "+f"(acc[0]), "+f"(acc[1]), "+f"(acc[2]), "+f"(acc[3])
        : "r"(a0), "r"(a1), "r"(a2), "r"(a3), "r"(b0), "r"(b1));
}

// warp-aggregated candidate push straight to global (one atomic per ballot)
__device__ __forceinline__ void wpush(bool pred, unsigned enc, int lane) {
    unsigned mask = __ballot_sync(0xffffffffu, pred);
    if (!mask) return;
    int leader = __ffs(mask) - 1;
    int base   = 0;
    if (lane == leader) base = atomicAdd(&g_ncand, __popc(mask));
    base = __shfl_sync(0xffffffffu, base, leader);
    if (pred) {
        int off = base + __popc(mask & ((1u << lane) - 1));
        if (off < CAND_CAP) g_cand[off] = enc;
    }
}

// ---------------------------------------------------------------------------
// Kernel 1 (single fused pass): tf32 GEMM of m[n,k] = 2*z.cb - e_sq with
// online per-row running max; enqueue every (n,k) with m > runmax - MARGIN.
// Guarantee: the exact winner k* satisfies m_ap(k*) >= globalmax_ap - 2eps
// > anymax - MARGIN (MARGIN=2e-3 >> 2eps~4.8e-4), so it is always enqueued
// regardless of prefix state of the running max.
// ---------------------------------------------------------------------------
__global__ __launch_bounds__(256, 2)
void approx_kernel(const float* __restrict__ z, const float* __restrict__ cb) {
    __shared__ unsigned uA[BM][36];      // z tile (tf32 bits), pad -> conflict-free
    __shared__ unsigned uB[BN][36];      // cb tile

    const int tid  = threadIdx.x;
    const int lane = tid & 31;
    const int warp = tid >> 5;
    const int wr = warp >> 1, wc = warp & 1;
    const int g = lane >> 2, t = lane & 3;
    const int row0 = blockIdx.x * BM;

    // slot s -> row r = wr*32 + (s>>1)*16 + (s&1)*8 + g
    float runmax[4];
    #pragma unroll
    for (int s = 0; s < 4; s++) runmax[s] = -3.4e38f;

    for (int kc = 0; kc < KCODES; kc += BN) {
        float acc[2][8][4];
        #pragma unroll
        for (int mf = 0; mf < 2; mf++)
            #pragma unroll
            for (int nf = 0; nf < 8; nf++)
                #pragma unroll
                for (int q = 0; q < 4; q++) acc[mf][nf][q] = 0.f;

        for (int dc = 0; dc < DIM; dc += BD) {
            __syncthreads();
            #pragma unroll
            for (int lph = 0; lph < 4; lph++) {
                int f  = tid + lph * 256;      // 0..1023
                int r  = f >> 3;
                int dq = (f & 7) << 2;
                float4 v = *(const float4*)(z + (size_t)(row0 + r) * DIM + dc + dq);
                asm("cvt.rna.tf32.f32 %0, %1;" : "=r"(uA[r][dq + 0]) : "f"(v.x));
                asm("cvt.rna.tf32.f32 %0, %1;" : "=r"(uA[r][dq + 1]) : "f"(v.y));
                asm("cvt.rna.tf32.f32 %0, %1;" : "=r"(uA[r][dq + 2]) : "f"(v.z));
                asm("cvt.rna.tf32.f32 %0, %1;" : "=r"(uA[r][dq + 3]) : "f"(v.w));
                float4 w = *(const float4*)(cb + (size_t)(kc + r) * DIM + dc + dq);
                asm("cvt.rna.tf32.f32 %0, %1;" : "=r"(uB[r][dq + 0]) : "f"(w.x));
                asm("cvt.rna.tf32.f32 %0, %1;" : "=r"(uB[r][dq + 1]) : "f"(w.y));
                asm("cvt.rna.tf32.f32 %0, %1;" : "=r"(uB[r][dq + 2]) : "f"(w.z));
                asm("cvt.rna.tf32.f32 %0, %1;" : "=r"(uB[r][dq + 3]) : "f"(w.w));
            }
            __syncthreads();

            #pragma unroll
            for (int ks = 0; ks < BD; ks += 8) {
                unsigned af[2][4];
                #pragma unroll
                for (int mf = 0; mf < 2; mf++) {
                    int ar = wr * 32 + mf * 16 + g;
                    af[mf][0] = uA[ar][ks + t];
                    af[mf][1] = uA[ar + 8][ks + t];
                    af[mf][2] = uA[ar][ks + t + 4];
                    af[mf][3] = uA[ar + 8][ks + t + 4];
                }
                #pragma unroll
                for (int nf = 0; nf < 8; nf++) {
                    int bn = wc * 64 + nf * 8 + g;
                    unsigned b0 = uB[bn][ks + t];
                    unsigned b1 = uB[bn][ks + t + 4];
                    mma_tf32(acc[0][nf], af[0][0], af[0][1], af[0][2], af[0][3], b0, b1);
                    mma_tf32(acc[1][nf], af[1][0], af[1][1], af[1][2], af[1][3], b0, b1);
                }
            }
        }

        // ---- epilogue pass A: chunk max per row slot ----
        float vmax[4];
        #pragma unroll
        for (int s = 0; s < 4; s++) vmax[s] = -3.4e38f;
        #pragma unroll
        for (int mf = 0; mf < 2; mf++)
            #pragma unroll
            for (int nf = 0; nf < 8; nf++) {
                int c0 = kc + wc * 64 + nf * 8 + 2 * t;
                float e0 = g_esq[c0], e1 = g_esq[c0 + 1];
                float m00 = __fmaf_rn(2.f, acc[mf][nf][0], -e0);
                float m01 = __fmaf_rn(2.f, acc[mf][nf][1], -e1);
                float m10 = __fmaf_rn(2.f, acc[mf][nf][2], -e0);
                float m11 = __fmaf_rn(2.f, acc[mf][nf][3], -e1);
                vmax[mf * 2]     = fmaxf(vmax[mf * 2],     fmaxf(m00, m01));
                vmax[mf * 2 + 1] = fmaxf(vmax[mf * 2 + 1], fmaxf(m10, m11));
            }
        #pragma unroll
        for (int s = 0; s < 4; s++) {
            float v = vmax[s];
            v = fmaxf(v, __shfl_xor_sync(0xffffffffu, v, 1));   // reduce over t lanes
            v = fmaxf(v, __shfl_xor_sync(0xffffffffu, v, 2));
            runmax[s] = fmaxf(runmax[s], v);
        }

        // ---- epilogue pass B: enqueue m > runmax - MARGIN (ballot -> global) ----
        #pragma unroll
        for (int mf = 0; mf < 2; mf++) {
            float thr0 = runmax[mf * 2] - MARGIN;
            float thr1 = runmax[mf * 2 + 1] - MARGIN;
            int r0 = row0 + wr * 32 + mf * 16 + g;
            #pragma unroll
            for (int nf = 0; nf < 8; nf++) {
                int c0 = kc + wc * 64 + nf * 8 + 2 * t;
                float e0 = g_esq[c0], e1 = g_esq[c0 + 1];
                float m00 = __fmaf_rn(2.f, acc[mf][nf][0], -e0);
                float m01 = __fmaf_rn(2.f, acc[mf][nf][1], -e1);
                float m10 = __fmaf_rn(2.f, acc[mf][nf][2], -e0);
                float m11 = __fmaf_rn(2.f, acc[mf][nf][3], -e1);
                wpush(m00 > thr0, ((unsigned)r0       << 10) | (unsigned)c0,       lane);
                wpush(m01 > thr0, ((unsigned)r0       << 10) | (unsigned)(c0 + 1), lane);
                wpush(m10 > thr1, ((unsigned)(r0 + 8) << 10) | (unsigned)c0,       lane);
                wpush(m11 > thr1, ((unsigned)(r0 + 8) << 10) | (unsigned)(c0 + 1), lane);
            }
        }
    }
}

// ---------------------------------------------------------------------------
// Kernel 2: exact rescore — bit-identical to R3's winning math: sequential
// fp32 fma chain d=0..255 (float4 loads, in-order), d = fl(fl(S-2c)+e);
// atomicMin on (distbits<<32 | code) -> min dist, ties -> lowest code.
// ---------------------------------------------------------------------------
__global__ void rescore_kernel(const float* __restrict__ z, const float* __restrict__ cb) {
    int n = g_ncand;
    if (n > CAND_CAP) n = CAND_CAP;
    for (int i = blockIdx.x * blockDim.x + threadIdx.x; i < n; i += gridDim.x * blockDim.x) {
        unsigned pc = g_cand[i];
        int row  = pc >> 10;
        int code = pc & 1023;
        const float4* zp = (const float4*)(z  + (size_t)row  * DIM);
        const float4* cp = (const float4*)(cb + (size_t)code * DIM);
        float c = 0.f;
        #pragma unroll 8
        for (int d4 = 0; d4 < DIM / 4; d4++) {
            float4 a = __ldg(zp + d4);
            float4 b = __ldg(cp + d4);
            c = __fmaf_rn(a.x, b.x, c);
            c = __fmaf_rn(a.y, b.y, c);
            c = __fmaf_rn(a.z, b.z, c);
            c = __fmaf_rn(a.w, b.w, c);
        }
        float dex = __fadd_rn(__fadd_rn(g_S[row], __fmul_rn(-2.f, c)), g_esq[code]);
        ull key = ((ull)__float_as_uint(dex) << 32) | (unsigned)code;
        atomicMin(&g_best[row], key);
    }
}

// ---------------------------------------------------------------------------
// Kernel 3: z_q = codebook[idx], per-block partial sums of (z_q - z_e)^2
// ---------------------------------------------------------------------------
__global__ void gather_loss_kernel(const float* __restrict__ z,
                                   const float* __restrict__ cb,
                                   float* __restrict__ out) {
    const int b   = blockIdx.x;
    const int tid = threadIdx.x;
    float s = 0.f;
    #pragma unroll
    for (int l = 0; l < 8; l++) {
        int f   = tid + l * 256;
        int r   = f >> 6;
        int c   = (f & 63) << 2;
        int row = b * 32 + r;
        int code = (int)(unsigned)(g_best[row] & 1023ull);
        float4 q  = *(const float4*)(cb + (size_t)code * DIM + c);
        float4 ze = *(const float4*)(z  + (size_t)row  * DIM + c);
        *(float4*)(out + (size_t)row * DIM + c) = q;
        float dx = q.x - ze.x, dy = q.y - ze.y, dz = q.z - ze.z, dw = q.w - ze.w;
        s += dx * dx + dy * dy + dz * dz + dw * dw;
    }
    __shared__ float red[256];
    red[tid] = s;
    __syncthreads();
    #pragma unroll
    for (int off = 128; off; off >>= 1) {
        if (tid < off) red[tid] += red[tid + off];
        __syncthreads();
    }
    if (tid == 0) g_partials[b] = red[0];
}

// ---------------------------------------------------------------------------
// Kernel 4: final deterministic loss reduction; write scalar(s) after z_q
// ---------------------------------------------------------------------------
__global__ void finalize_kernel(float* __restrict__ out, int out_size) {
    __shared__ double red[256];
    const int tid = threadIdx.x;
    double s = 0.0;
    for (int i = tid; i < 2048; i += 256) s += (double)g_partials[i];
    red[tid] = s;
    __syncthreads();
    #pragma unroll
    for (int off = 128; off; off >>= 1) {
        if (tid < off) red[tid] += red[tid + off];
        __syncthreads();
    }
    if (tid == 0) {
        float loss = (float)(red[0] / (double)((long)N_ROWS * DIM));
        for (long i = (long)N_ROWS * DIM; i < (long)out_size; i++) out[i] = loss;
    }
}

// ---------------------------------------------------------------------------
extern "C" void kernel_launch(void* const* d_in, const int* in_sizes, int n_in,
                              void* d_out, int out_size) {
    const float* z  = (const float*)d_in[0];
    const float* cb = (const float*)d_in[1];
    if (n_in >= 2 && in_sizes[0] == KCODES * DIM && in_sizes[1] == N_ROWS * DIM) {
        const float* t = z; z = cb; cb = t;
    }
    float* out = (float*)d_out;

    esq_kernel<<<KCODES / 8, 256>>>(cb);             // also zeroes g_ncand
    s_kernel<<<N_ROWS / 16, 256>>>(z);               // also inits g_best
    approx_kernel<<<N_ROWS / BM, 256>>>(z, cb);      // fused GEMM + online max + candidates
    rescore_kernel<<<1024, 256>>>(z, cb);            // exact winners
    gather_loss_kernel<<<N_ROWS / 32, 256>>>(z, cb, out);
    finalize_kernel<<<1, 256>>>(out, out_size);
}

// round 13
// speedup vs baseline: 3.0595x; 1.2996x over previous
#include <cuda_runtime.h>

#define N_ROWS 65536
#define DIM    256
#define KCODES 1024

#define BM 128
#define BN 128
#define BD 32
#define CAND_CAP (2 * 1024 * 1024)
#define MARGIN   2e-3f

typedef unsigned long long ull;

// Scratch (no allocations allowed in kernel_launch)
__device__ float    g_esq[KCODES];
__device__ float    g_S[N_ROWS];
__device__ float    g_maxm[N_ROWS];
__device__ ull      g_best[N_ROWS];
__device__ uint2    g_cand[CAND_CAP];
__device__ int      g_ncand;
__device__ float    g_partials[2048];

// ---------------------------------------------------------------------------
// Kernel 0: e_sq[k] = ||codebook[k]||^2 (order-insensitive; validated R3)
// ---------------------------------------------------------------------------
__global__ void esq_kernel(const float* __restrict__ cb) {
    if (blockIdx.x == 0 && threadIdx.x == 0) g_ncand = 0;
    int warp = (blockIdx.x * blockDim.x + threadIdx.x) >> 5;
    int lane = threadIdx.x & 31;
    if (warp >= KCODES) return;
    const float4* row = (const float4*)(cb + warp * DIM);
    float s = 0.f;
    #pragma unroll
    for (int i = lane; i < DIM / 4; i += 32) {
        float4 v = row[i];
        s += v.x * v.x + v.y * v.y + v.z * v.z + v.w * v.w;
    }
    #pragma unroll
    for (int off = 16; off; off >>= 1) s += __shfl_xor_sync(0xffffffff, s, off);
    if (lane == 0) g_esq[warp] = s;
}

// ---------------------------------------------------------------------------
// Kernel 0b: S[n] = ||z[n]||^2, bit-exact IC=4 order (validated R3/R4).
// Also initializes g_best[row].
// ---------------------------------------------------------------------------
__global__ void s_kernel(const float* __restrict__ z) {
    int warp = (blockIdx.x * blockDim.x + threadIdx.x) >> 5;
    int lane = threadIdx.x & 31;
    int j    = lane & 15;
    long row = (long)warp * 2 + (lane >> 4);
    const float* p = z + row * DIM;
    float a = 0.f;
    #pragma unroll
    for (int i = 0; i < 16; i++) {
        float v = p[i * 16 + j];
        a = __fmaf_rn(v, v, a);
    }
    unsigned m = 0xffffffffu;
    float t1 = __shfl_down_sync(m, a, 4, 16);
    float t2 = __shfl_down_sync(m, a, 8, 16);
    float t3 = __shfl_down_sync(m, a, 12, 16);
    float u  = __fadd_rn(__fadd_rn(__fadd_rn(a, t1), t2), t3);
    float u1 = __shfl_down_sync(m, u, 1, 16);
    float u2 = __shfl_down_sync(m, u, 2, 16);
    float u3 = __shfl_down_sync(m, u, 3, 16);
    if (j == 0) {
        g_S[row]    = __fadd_rn(__fadd_rn(u, u1), __fadd_rn(u2, u3));
        g_best[row] = ~0ull;
    }
}

// ---------------------------------------------------------------------------
// tf32 mma helper
// ---------------------------------------------------------------------------
__device__ __forceinline__ void mma_tf32(float acc[4],
                                         unsigned a0, unsigned a1, unsigned a2, unsigned a3,
                                         unsigned b0, unsigned b1) {
    asm volatile(
        "mma.sync.aligned.m16n8k8.row.col.f32.tf32.tf32.f32 "
        "{%0,%1,%2,%3}, {%4,%5,%6,%7}, {%8,%9}, {%0,%1,%2,%3};"
        : "+f"(acc[0]), "+f"(acc[1]), "+f"(acc[2]), "+f"(acc[3])
        : "r"(a0), "r"(a1), "r"(a2), "r"(a3), "r"(b0), "r"(b1));
}

// warp-aggregated candidate push (enc + approx score) to global
__device__ __forceinline__ void wpush(bool pred, unsigned enc, float m, int lane) {
    unsigned mask = __ballot_sync(0xffffffffu, pred);
    if (!mask) return;
    int leader = __ffs(mask) - 1;
    int base   = 0;
    if (lane == leader) base = atomicAdd(&g_ncand, __popc(mask));
    base = __shfl_sync(0xffffffffu, base, leader);
    if (pred) {
        int off = base + __popc(mask & ((1u << lane) - 1));
        if (off < CAND_CAP) g_cand[off] = make_uint2(enc, __float_as_uint(m));
    }
}

// ---------------------------------------------------------------------------
// Kernel 1 (single fused pass): tf32 GEMM of m[n,k] = 2*z.cb - e_sq with
// online per-row running max; enqueue every (n,k) with m > runmax - MARGIN,
// carrying the approx score. Final per-row max is published to g_maxm so the
// rescore pass can filter prefix-weak enqueues down to the true margin set.
// Winner guarantee: m_ap(k*) >= finalmax - 2eps > finalmax - MARGIN, and
// runmax <= finalmax, so k* is always enqueued AND always passes the filter.
// ---------------------------------------------------------------------------
__global__ __launch_bounds__(256, 2)
void approx_kernel(const float* __restrict__ z, const float* __restrict__ cb) {
    __shared__ unsigned uA[BM][36];      // z tile (tf32 bits), pad -> conflict-free
    __shared__ unsigned uB[BN][36];      // cb tile
    __shared__ float    sMaxA[BM];       // per-row max from wc=0 warps
    __shared__ float    sMaxB[BM];       // per-row max from wc=1 warps

    const int tid  = threadIdx.x;
    const int lane = tid & 31;
    const int warp = tid >> 5;
    const int wr = warp >> 1, wc = warp & 1;
    const int g = lane >> 2, t = lane & 3;
    const int row0 = blockIdx.x * BM;

    // slot s -> row r = wr*32 + (s>>1)*16 + (s&1)*8 + g
    float runmax[4];
    #pragma unroll
    for (int s = 0; s < 4; s++) runmax[s] = -3.4e38f;

    for (int kc = 0; kc < KCODES; kc += BN) {
        float acc[2][8][4];
        #pragma unroll
        for (int mf = 0; mf < 2; mf++)
            #pragma unroll
            for (int nf = 0; nf < 8; nf++)
                #pragma unroll
                for (int q = 0; q < 4; q++) acc[mf][nf][q] = 0.f;

        for (int dc = 0; dc < DIM; dc += BD) {
            __syncthreads();
            #pragma unroll
            for (int lph = 0; lph < 4; lph++) {
                int f  = tid + lph * 256;      // 0..1023
                int r  = f >> 3;
                int dq = (f & 7) << 2;
                float4 v = *(const float4*)(z + (size_t)(row0 + r) * DIM + dc + dq);
                asm("cvt.rna.tf32.f32 %0, %1;" : "=r"(uA[r][dq + 0]) : "f"(v.x));
                asm("cvt.rna.tf32.f32 %0, %1;" : "=r"(uA[r][dq + 1]) : "f"(v.y));
                asm("cvt.rna.tf32.f32 %0, %1;" : "=r"(uA[r][dq + 2]) : "f"(v.z));
                asm("cvt.rna.tf32.f32 %0, %1;" : "=r"(uA[r][dq + 3]) : "f"(v.w));
                float4 w = *(const float4*)(cb + (size_t)(kc + r) * DIM + dc + dq);
                asm("cvt.rna.tf32.f32 %0, %1;" : "=r"(uB[r][dq + 0]) : "f"(w.x));
                asm("cvt.rna.tf32.f32 %0, %1;" : "=r"(uB[r][dq + 1]) : "f"(w.y));
                asm("cvt.rna.tf32.f32 %0, %1;" : "=r"(uB[r][dq + 2]) : "f"(w.z));
                asm("cvt.rna.tf32.f32 %0, %1;" : "=r"(uB[r][dq + 3]) : "f"(w.w));
            }
            __syncthreads();

            #pragma unroll
            for (int ks = 0; ks < BD; ks += 8) {
                unsigned af[2][4];
                #pragma unroll
                for (int mf = 0; mf < 2; mf++) {
                    int ar = wr * 32 + mf * 16 + g;
                    af[mf][0] = uA[ar][ks + t];
                    af[mf][1] = uA[ar + 8][ks + t];
                    af[mf][2] = uA[ar][ks + t + 4];
                    af[mf][3] = uA[ar + 8][ks + t + 4];
                }
                #pragma unroll
                for (int nf = 0; nf < 8; nf++) {
                    int bn = wc * 64 + nf * 8 + g;
                    unsigned b0 = uB[bn][ks + t];
                    unsigned b1 = uB[bn][ks + t + 4];
                    mma_tf32(acc[0][nf], af[0][0], af[0][1], af[0][2], af[0][3], b0, b1);
                    mma_tf32(acc[1][nf], af[1][0], af[1][1], af[1][2], af[1][3], b0, b1);
                }
            }
        }

        // ---- epilogue pass A: chunk max per row slot ----
        float vmax[4];
        #pragma unroll
        for (int s = 0; s < 4; s++) vmax[s] = -3.4e38f;
        #pragma unroll
        for (int mf = 0; mf < 2; mf++)
            #pragma unroll
            for (int nf = 0; nf < 8; nf++) {
                int c0 = kc + wc * 64 + nf * 8 + 2 * t;
                float e0 = g_esq[c0], e1 = g_esq[c0 + 1];
                float m00 = __fmaf_rn(2.f, acc[mf][nf][0], -e0);
                float m01 = __fmaf_rn(2.f, acc[mf][nf][1], -e1);
                float m10 = __fmaf_rn(2.f, acc[mf][nf][2], -e0);
                float m11 = __fmaf_rn(2.f, acc[mf][nf][3], -e1);
                vmax[mf * 2]     = fmaxf(vmax[mf * 2],     fmaxf(m00, m01));
                vmax[mf * 2 + 1] = fmaxf(vmax[mf * 2 + 1], fmaxf(m10, m11));
            }
        #pragma unroll
        for (int s = 0; s < 4; s++) {
            float v = vmax[s];
            v = fmaxf(v, __shfl_xor_sync(0xffffffffu, v, 1));   // reduce over t lanes
            v = fmaxf(v, __shfl_xor_sync(0xffffffffu, v, 2));
            runmax[s] = fmaxf(runmax[s], v);
        }

        // ---- epilogue pass B: enqueue m > runmax - MARGIN (ballot -> global) ----
        #pragma unroll
        for (int mf = 0; mf < 2; mf++) {
            float thr0 = runmax[mf * 2] - MARGIN;
            float thr1 = runmax[mf * 2 + 1] - MARGIN;
            int r0 = row0 + wr * 32 + mf * 16 + g;
            #pragma unroll
            for (int nf = 0; nf < 8; nf++) {
                int c0 = kc + wc * 64 + nf * 8 + 2 * t;
                float e0 = g_esq[c0], e1 = g_esq[c0 + 1];
                float m00 = __fmaf_rn(2.f, acc[mf][nf][0], -e0);
                float m01 = __fmaf_rn(2.f, acc[mf][nf][1], -e1);
                float m10 = __fmaf_rn(2.f, acc[mf][nf][2], -e0);
                float m11 = __fmaf_rn(2.f, acc[mf][nf][3], -e1);
                wpush(m00 > thr0, ((unsigned)r0       << 10) | (unsigned)c0,       m00, lane);
                wpush(m01 > thr0, ((unsigned)r0       << 10) | (unsigned)(c0 + 1), m01, lane);
                wpush(m10 > thr1, ((unsigned)(r0 + 8) << 10) | (unsigned)c0,       m10, lane);
                wpush(m11 > thr1, ((unsigned)(r0 + 8) << 10) | (unsigned)(c0 + 1), m11, lane);
            }
        }
    }

    // ---- publish final per-row max (combine the two wc halves) ----
    __syncthreads();
    if (t == 0) {
        float* dst = (wc == 0) ? sMaxA : sMaxB;
        #pragma unroll
        for (int s = 0; s < 4; s++) {
            int rl = wr * 32 + (s >> 1) * 16 + (s & 1) * 8 + g;
            dst[rl] = runmax[s];
        }
    }
    __syncthreads();
    if (tid < BM) g_maxm[row0 + tid] = fmaxf(sMaxA[tid], sMaxB[tid]);
}

// ---------------------------------------------------------------------------
// Kernel 2: filter by FINAL per-row max, then exact rescore — bit-identical
// to R3's winning math: sequential fp32 fma chain d=0..255 (float4 loads,
// in-order), d = fl(fl(S-2c)+e); atomicMin on (distbits<<32 | code).
// ---------------------------------------------------------------------------
__global__ void rescore_kernel(const float* __restrict__ z, const float* __restrict__ cb) {
    int n = g_ncand;
    if (n > CAND_CAP) n = CAND_CAP;
    for (int i = blockIdx.x * blockDim.x + threadIdx.x; i < n; i += gridDim.x * blockDim.x) {
        uint2 pc = g_cand[i];
        int row  = pc.x >> 10;
        // cheap coalesced filter against the final (true) per-row max
        if (__uint_as_float(pc.y) <= g_maxm[row] - MARGIN) continue;
        int code = pc.x & 1023;
        const float4* zp = (const float4*)(z  + (size_t)row  * DIM);
        const float4* cp = (const float4*)(cb + (size_t)code * DIM);
        float c = 0.f;
        #pragma unroll 8
        for (int d4 = 0; d4 < DIM / 4; d4++) {
            float4 a = __ldg(zp + d4);
            float4 b = __ldg(cp + d4);
            c = __fmaf_rn(a.x, b.x, c);
            c = __fmaf_rn(a.y, b.y, c);
            c = __fmaf_rn(a.z, b.z, c);
            c = __fmaf_rn(a.w, b.w, c);
        }
        float dex = __fadd_rn(__fadd_rn(g_S[row], __fmul_rn(-2.f, c)), g_esq[code]);
        ull key = ((ull)__float_as_uint(dex) << 32) | (unsigned)code;
        atomicMin(&g_best[row], key);
    }
}

// ---------------------------------------------------------------------------
// Kernel 3: z_q = codebook[idx], per-block partial sums of (z_q - z_e)^2
// ---------------------------------------------------------------------------
__global__ void gather_loss_kernel(const float* __restrict__ z,
                                   const float* __restrict__ cb,
                                   float* __restrict__ out) {
    const int b   = blockIdx.x;
    const int tid = threadIdx.x;
    float s = 0.f;
    #pragma unroll
    for (int l = 0; l < 8; l++) {
        int f   = tid + l * 256;
        int r   = f >> 6;
        int c   = (f & 63) << 2;
        int row = b * 32 + r;
        int code = (int)(unsigned)(g_best[row] & 1023ull);
        float4 q  = *(const float4*)(cb + (size_t)code * DIM + c);
        float4 ze = *(const float4*)(z  + (size_t)row  * DIM + c);
        *(float4*)(out + (size_t)row * DIM + c) = q;
        float dx = q.x - ze.x, dy = q.y - ze.y, dz = q.z - ze.z, dw = q.w - ze.w;
        s += dx * dx + dy * dy + dz * dz + dw * dw;
    }
    __shared__ float red[256];
    red[tid] = s;
    __syncthreads();
    #pragma unroll
    for (int off = 128; off; off >>= 1) {
        if (tid < off) red[tid] += red[tid + off];
        __syncthreads();
    }
    if (tid == 0) g_partials[b] = red[0];
}

// ---------------------------------------------------------------------------
// Kernel 4: final deterministic loss reduction; write scalar(s) after z_q
// ---------------------------------------------------------------------------
__global__ void finalize_kernel(float* __restrict__ out, int out_size) {
    __shared__ double red[256];
    const int tid = threadIdx.x;
    double s = 0.0;
    for (int i = tid; i < 2048; i += 256) s += (double)g_partials[i];
    red[tid] = s;
    __syncthreads();
    #pragma unroll
    for (int off = 128; off; off >>= 1) {
        if (tid < off) red[tid] += red[tid + off];
        __syncthreads();
    }
    if (tid == 0) {
        float loss = (float)(red[0] / (double)((long)N_ROWS * DIM));
        for (long i = (long)N_ROWS * DIM; i < (long)out_size; i++) out[i] = loss;
    }
}

// ---------------------------------------------------------------------------
extern "C" void kernel_launch(void* const* d_in, const int* in_sizes, int n_in,
                              void* d_out, int out_size) {
    const float* z  = (const float*)d_in[0];
    const float* cb = (const float*)d_in[1];
    if (n_in >= 2 && in_sizes[0] == KCODES * DIM && in_sizes[1] == N_ROWS * DIM) {
        const float* t = z; z = cb; cb = t;
    }
    float* out = (float*)d_out;

    esq_kernel<<<KCODES / 8, 256>>>(cb);             // also zeroes g_ncand
    s_kernel<<<N_ROWS / 16, 256>>>(z);               // also inits g_best
    approx_kernel<<<N_ROWS / BM, 256>>>(z, cb);      // fused GEMM + online max + candidates
    rescore_kernel<<<1024, 256>>>(z, cb);            // filter by final max + exact winners
    gather_loss_kernel<<<N_ROWS / 32, 256>>>(z, cb, out);
    finalize_kernel<<<1, 256>>>(out, out_size);
}

// round 15
// speedup vs baseline: 3.5378x; 1.1563x over previous
#include <cuda_runtime.h>
#include <cuda_bf16.h>

#define N_ROWS 65536
#define DIM    256
#define KCODES 1024

#define BM 128
#define BN 128
#define BD 32
#define CAND_CAP (2 * 1024 * 1024)
#define MARGIN   2e-3f

typedef unsigned long long ull;

// Scratch (no allocations allowed in kernel_launch)
__device__ float    g_esq[KCODES];
__device__ float    g_S[N_ROWS];
__device__ float    g_maxm[N_ROWS];
__device__ ull      g_best[N_ROWS];
__device__ uint2    g_cand[CAND_CAP];
__device__ int      g_ncand;
__device__ float    g_partials[2048];

// ---------------------------------------------------------------------------
// Kernel 0: e_sq[k] = ||codebook[k]||^2 (order-insensitive; validated R3)
// ---------------------------------------------------------------------------
__global__ void esq_kernel(const float* __restrict__ cb) {
    if (blockIdx.x == 0 && threadIdx.x == 0) g_ncand = 0;
    int warp = (blockIdx.x * blockDim.x + threadIdx.x) >> 5;
    int lane = threadIdx.x & 31;
    if (warp >= KCODES) return;
    const float4* row = (const float4*)(cb + warp * DIM);
    float s = 0.f;
    #pragma unroll
    for (int i = lane; i < DIM / 4; i += 32) {
        float4 v = row[i];
        s += v.x * v.x + v.y * v.y + v.z * v.z + v.w * v.w;
    }
    #pragma unroll
    for (int off = 16; off; off >>= 1) s += __shfl_xor_sync(0xffffffff, s, off);
    if (lane == 0) g_esq[warp] = s;
}

// ---------------------------------------------------------------------------
// Kernel 0b: S[n] = ||z[n]||^2, bit-exact IC=4 order (validated R3/R4).
// Also initializes g_best[row].
// ---------------------------------------------------------------------------
__global__ void s_kernel(const float* __restrict__ z) {
    int warp = (blockIdx.x * blockDim.x + threadIdx.x) >> 5;
    int lane = threadIdx.x & 31;
    int j    = lane & 15;
    long row = (long)warp * 2 + (lane >> 4);
    const float* p = z + row * DIM;
    float a = 0.f;
    #pragma unroll
    for (int i = 0; i < 16; i++) {
        float v = p[i * 16 + j];
        a = __fmaf_rn(v, v, a);
    }
    unsigned m = 0xffffffffu;
    float t1 = __shfl_down_sync(m, a, 4, 16);
    float t2 = __shfl_down_sync(m, a, 8, 16);
    float t3 = __shfl_down_sync(m, a, 12, 16);
    float u  = __fadd_rn(__fadd_rn(__fadd_rn(a, t1), t2), t3);
    float u1 = __shfl_down_sync(m, u, 1, 16);
    float u2 = __shfl_down_sync(m, u, 2, 16);
    float u3 = __shfl_down_sync(m, u, 3, 16);
    if (j == 0) {
        g_S[row]    = __fadd_rn(__fadd_rn(u, u1), __fadd_rn(u2, u3));
        g_best[row] = ~0ull;
    }
}

// ---------------------------------------------------------------------------
// bf16 mma helper (m16n8k16; same C-fragment mapping as the tf32 m16n8k8)
// ---------------------------------------------------------------------------
__device__ __forceinline__ void mma_bf16(float acc[4],
                                         unsigned a0, unsigned a1, unsigned a2, unsigned a3,
                                         unsigned b0, unsigned b1) {
    asm volatile(
        "mma.sync.aligned.m16n8k16.row.col.f32.bf16.bf16.f32 "
        "{%0,%1,%2,%3}, {%4,%5,%6,%7}, {%8,%9}, {%0,%1,%2,%3};"
        : "+f"(acc[0]), "+f"(acc[1]), "+f"(acc[2]), "+f"(acc[3])
        : "r"(a0), "r"(a1), "r"(a2), "r"(a3), "r"(b0), "r"(b1));
}

__device__ __forceinline__ unsigned pack_bf16x2(float lo, float hi) {
    __nv_bfloat162 h = __floats2bfloat162_rn(lo, hi);   // x=lo (low 16), y=hi
    return *reinterpret_cast<unsigned*>(&h);
}

// warp-aggregated candidate push (enc + approx score) to global
__device__ __forceinline__ void wpush(bool pred, unsigned enc, float m, int lane) {
    unsigned mask = __ballot_sync(0xffffffffu, pred);
    if (!mask) return;
    int leader = __ffs(mask) - 1;
    int base   = 0;
    if (lane == leader) base = atomicAdd(&g_ncand, __popc(mask));
    base = __shfl_sync(0xffffffffu, base, leader);
    if (pred) {
        int off = base + __popc(mask & ((1u << lane) - 1));
        if (off < CAND_CAP) g_cand[off] = make_uint2(enc, __float_as_uint(m));
    }
}

// ---------------------------------------------------------------------------
// Kernel 1 (single fused pass): bf16 mma GEMM of m[n,k] = 2*z.cb - e_sq with
// online per-row running max; enqueue every (n,k) with m > runmax - MARGIN
// (gated by one pre-ballot per fragment group), carrying the approx score.
// Final per-row max is published to g_maxm; rescore filters against it.
// Winner guarantee: |m_ap - m_exact| <= eps with 2*eps(worst) ~ 1.6e-3 <
// MARGIN is conservative even adversarially; winner always enqueued AND
// always passes the final filter. Exact rescore decides all indices.
// ---------------------------------------------------------------------------
__global__ __launch_bounds__(256, 2)
void approx_kernel(const float* __restrict__ z, const float* __restrict__ cb) {
    __shared__ unsigned uA[BM][20];      // z tile, bf16x2 (k pairs), pad -> conflict-free
    __shared__ unsigned uB[BN][20];      // cb tile
    __shared__ float    sMaxA[BM];       // per-row max from wc=0 warps
    __shared__ float    sMaxB[BM];       // per-row max from wc=1 warps

    const int tid  = threadIdx.x;
    const int lane = tid & 31;
    const int warp = tid >> 5;
    const int wr = warp >> 1, wc = warp & 1;
    const int g = lane >> 2, t = lane & 3;
    const int row0 = blockIdx.x * BM;

    // slot s -> row r = wr*32 + (s>>1)*16 + (s&1)*8 + g
    float runmax[4];
    #pragma unroll
    for (int s = 0; s < 4; s++) runmax[s] = -3.4e38f;

    for (int kc = 0; kc < KCODES; kc += BN) {
        float acc[2][8][4];
        #pragma unroll
        for (int mf = 0; mf < 2; mf++)
            #pragma unroll
            for (int nf = 0; nf < 8; nf++)
                #pragma unroll
                for (int q = 0; q < 4; q++) acc[mf][nf][q] = 0.f;

        for (int dc = 0; dc < DIM; dc += BD) {
            __syncthreads();
            #pragma unroll
            for (int lph = 0; lph < 4; lph++) {
                int f = tid + lph * 256;       // 0..1023
                int r = f >> 3;
                int q = f & 7;                 // float4 index within 32-float row chunk
                float4 v = *(const float4*)(z + (size_t)(row0 + r) * DIM + dc + q * 4);
                uA[r][2 * q]     = pack_bf16x2(v.x, v.y);
                uA[r][2 * q + 1] = pack_bf16x2(v.z, v.w);
                float4 w = *(const float4*)(cb + (size_t)(kc + r) * DIM + dc + q * 4);
                uB[r][2 * q]     = pack_bf16x2(w.x, w.y);
                uB[r][2 * q + 1] = pack_bf16x2(w.z, w.w);
            }
            __syncthreads();

            #pragma unroll
            for (int ks = 0; ks < 2; ks++) {   // two k16 steps per BD=32
                int j0 = ks * 8;
                unsigned af[2][4];
                #pragma unroll
                for (int mf = 0; mf < 2; mf++) {
                    int ar = wr * 32 + mf * 16 + g;
                    af[mf][0] = uA[ar][j0 + t];          // row g,   k lo
                    af[mf][1] = uA[ar + 8][j0 + t];      // row g+8, k lo
                    af[mf][2] = uA[ar][j0 + t + 4];      // row g,   k hi
                    af[mf][3] = uA[ar + 8][j0 + t + 4];  // row g+8, k hi
                }
                #pragma unroll
                for (int nf = 0; nf < 8; nf++) {
                    int bn = wc * 64 + nf * 8 + g;
                    unsigned b0 = uB[bn][j0 + t];
                    unsigned b1 = uB[bn][j0 + t + 4];
                    mma_bf16(acc[0][nf], af[0][0], af[0][1], af[0][2], af[0][3], b0, b1);
                    mma_bf16(acc[1][nf], af[1][0], af[1][1], af[1][2], af[1][3], b0, b1);
                }
            }
        }

        // ---- epilogue pass A: chunk max per row slot ----
        float vmax[4];
        #pragma unroll
        for (int s = 0; s < 4; s++) vmax[s] = -3.4e38f;
        #pragma unroll
        for (int mf = 0; mf < 2; mf++)
            #pragma unroll
            for (int nf = 0; nf < 8; nf++) {
                int c0 = kc + wc * 64 + nf * 8 + 2 * t;
                float e0 = g_esq[c0], e1 = g_esq[c0 + 1];
                float m00 = __fmaf_rn(2.f, acc[mf][nf][0], -e0);
                float m01 = __fmaf_rn(2.f, acc[mf][nf][1], -e1);
                float m10 = __fmaf_rn(2.f, acc[mf][nf][2], -e0);
                float m11 = __fmaf_rn(2.f, acc[mf][nf][3], -e1);
                vmax[mf * 2]     = fmaxf(vmax[mf * 2],     fmaxf(m00, m01));
                vmax[mf * 2 + 1] = fmaxf(vmax[mf * 2 + 1], fmaxf(m10, m11));
            }
        #pragma unroll
        for (int s = 0; s < 4; s++) {
            float v = vmax[s];
            v = fmaxf(v, __shfl_xor_sync(0xffffffffu, v, 1));   // reduce over t lanes
            v = fmaxf(v, __shfl_xor_sync(0xffffffffu, v, 2));
            runmax[s] = fmaxf(runmax[s], v);
        }

        // ---- epilogue pass B: enqueue m > runmax - MARGIN (gated ballots) ----
        #pragma unroll
        for (int mf = 0; mf < 2; mf++) {
            float thr0 = runmax[mf * 2] - MARGIN;
            float thr1 = runmax[mf * 2 + 1] - MARGIN;
            int r0 = row0 + wr * 32 + mf * 16 + g;
            #pragma unroll
            for (int nf = 0; nf < 8; nf++) {
                int c0 = kc + wc * 64 + nf * 8 + 2 * t;
                float e0 = g_esq[c0], e1 = g_esq[c0 + 1];
                float m00 = __fmaf_rn(2.f, acc[mf][nf][0], -e0);
                float m01 = __fmaf_rn(2.f, acc[mf][nf][1], -e1);
                float m10 = __fmaf_rn(2.f, acc[mf][nf][2], -e0);
                float m11 = __fmaf_rn(2.f, acc[mf][nf][3], -e1);
                bool p0 = m00 > thr0, p1 = m01 > thr0;
                bool p2 = m10 > thr1, p3 = m11 > thr1;
                unsigned any = __ballot_sync(0xffffffffu, p0 | p1 | p2 | p3);
                if (any) {                       // warp-uniform branch
                    wpush(p0, ((unsigned)r0       << 10) | (unsigned)c0,       m00, lane);
                    wpush(p1, ((unsigned)r0       << 10) | (unsigned)(c0 + 1), m01, lane);
                    wpush(p2, ((unsigned)(r0 + 8) << 10) | (unsigned)c0,       m10, lane);
                    wpush(p3, ((unsigned)(r0 + 8) << 10) | (unsigned)(c0 + 1), m11, lane);
                }
            }
        }
    }

    // ---- publish final per-row max (combine the two wc halves) ----
    __syncthreads();
    if (t == 0) {
        float* dst = (wc == 0) ? sMaxA : sMaxB;
        #pragma unroll
        for (int s = 0; s < 4; s++) {
            int rl = wr * 32 + (s >> 1) * 16 + (s & 1) * 8 + g;
            dst[rl] = runmax[s];
        }
    }
    __syncthreads();
    if (tid < BM) g_maxm[row0 + tid] = fmaxf(sMaxA[tid], sMaxB[tid]);
}

// ---------------------------------------------------------------------------
// Kernel 2: filter by FINAL per-row max, then exact rescore — bit-identical
// to R3's winning math: sequential fp32 fma chain d=0..255 (float4 loads,
// in-order), d = fl(fl(S-2c)+e); atomicMin on (distbits<<32 | code).
// ---------------------------------------------------------------------------
__global__ void rescore_kernel(const float* __restrict__ z, const float* __restrict__ cb) {
    int n = g_ncand;
    if (n > CAND_CAP) n = CAND_CAP;
    for (int i = blockIdx.x * blockDim.x + threadIdx.x; i < n; i += gridDim.x * blockDim.x) {
        uint2 pc = g_cand[i];
        int row  = pc.x >> 10;
        if (__uint_as_float(pc.y) <= g_maxm[row] - MARGIN) continue;
        int code = pc.x & 1023;
        const float4* zp = (const float4*)(z  + (size_t)row  * DIM);
        const float4* cp = (const float4*)(cb + (size_t)code * DIM);
        float c = 0.f;
        #pragma unroll 8
        for (int d4 = 0; d4 < DIM / 4; d4++) {
            float4 a = __ldg(zp + d4);
            float4 b = __ldg(cp + d4);
            c = __fmaf_rn(a.x, b.x, c);
            c = __fmaf_rn(a.y, b.y, c);
            c = __fmaf_rn(a.z, b.z, c);
            c = __fmaf_rn(a.w, b.w, c);
        }
        float dex = __fadd_rn(__fadd_rn(g_S[row], __fmul_rn(-2.f, c)), g_esq[code]);
        ull key = ((ull)__float_as_uint(dex) << 32) | (unsigned)code;
        atomicMin(&g_best[row], key);
    }
}

// ---------------------------------------------------------------------------
// Kernel 3: z_q = codebook[idx], per-block partial sums of (z_q - z_e)^2
// ---------------------------------------------------------------------------
__global__ void gather_loss_kernel(const float* __restrict__ z,
                                   const float* __restrict__ cb,
                                   float* __restrict__ out) {
    const int b   = blockIdx.x;
    const int tid = threadIdx.x;
    float s = 0.f;
    #pragma unroll
    for (int l = 0; l < 8; l++) {
        int f   = tid + l * 256;
        int r   = f >> 6;
        int c   = (f & 63) << 2;
        int row = b * 32 + r;
        int code = (int)(unsigned)(g_best[row] & 1023ull);
        float4 q  = *(const float4*)(cb + (size_t)code * DIM + c);
        float4 ze = *(const float4*)(z  + (size_t)row  * DIM + c);
        *(float4*)(out + (size_t)row * DIM + c) = q;
        float dx = q.x - ze.x, dy = q.y - ze.y, dz = q.z - ze.z, dw = q.w - ze.w;
        s += dx * dx + dy * dy + dz * dz + dw * dw;
    }
    __shared__ float red[256];
    red[tid] = s;
    __syncthreads();
    #pragma unroll
    for (int off = 128; off; off >>= 1) {
        if (tid < off) red[tid] += red[tid + off];
        __syncthreads();
    }
    if (tid == 0) g_partials[b] = red[0];
}

// ---------------------------------------------------------------------------
// Kernel 4: final deterministic loss reduction; write scalar(s) after z_q
// ---------------------------------------------------------------------------
__global__ void finalize_kernel(float* __restrict__ out, int out_size) {
    __shared__ double red[256];
    const int tid = threadIdx.x;
    double s = 0.0;
    for (int i = tid; i < 2048; i += 256) s += (double)g_partials[i];
    red[tid] = s;
    __syncthreads();
    #pragma unroll
    for (int off = 128; off; off >>= 1) {
        if (tid < off) red[tid] += red[tid + off];
        __syncthreads();
    }
    if (tid == 0) {
        float loss = (float)(red[0] / (double)((long)N_ROWS * DIM));
        for (long i = (long)N_ROWS * DIM; i < (long)out_size; i++) out[i] = loss;
    }
}

// ---------------------------------------------------------------------------
extern "C" void kernel_launch(void* const* d_in, const int* in_sizes, int n_in,
                              void* d_out, int out_size) {
    const float* z  = (const float*)d_in[0];
    const float* cb = (const float*)d_in[1];
    if (n_in >= 2 && in_sizes[0] == KCODES * DIM && in_sizes[1] == N_ROWS * DIM) {
        const float* t = z; z = cb; cb = t;
    }
    float* out = (float*)d_out;

    esq_kernel<<<KCODES / 8, 256>>>(cb);             // also zeroes g_ncand
    s_kernel<<<N_ROWS / 16, 256>>>(z);               // also inits g_best
    approx_kernel<<<N_ROWS / BM, 256>>>(z, cb);      // fused bf16 GEMM + online max + candidates
    rescore_kernel<<<1024, 256>>>(z, cb);            // filter by final max + exact winners
    gather_loss_kernel<<<N_ROWS / 32, 256>>>(z, cb, out);
    finalize_kernel<<<1, 256>>>(out, out_size);
}